// round 6
// baseline (speedup 1.0000x reference)
#include <cuda_runtime.h>

// SSIM, fused separable 11x11 Gaussian (sigma=1.5), B=16,C=3,H=W=512, fp32.
// Round-6: issue-bound -> cut instructions. Each thread computes 2 ADJACENT
// output columns sharing the 11-tap window: LDS.64 vector loads (7 per map vs
// 22 scalar), shared squares (24 FMUL vs 44). s/d reformulation (4 convs).
// 64 threads per 128x64 tile, cp.async double-buffered 11-row groups,
// 2-col register ring (88 regs), fused finalize via atomic ticket.

constexpr int IMG_H = 512;
constexpr int IMG_W = 512;
constexpr int N_IMG = 48;
constexpr int RAD   = 5;
constexpr int WS    = 11;
constexpr int TW    = 128;            // tile width; 2 cols per thread
constexpr int TH    = 64;
constexpr int LPAD  = 8;              // 16B-aligned left halo
constexpr int COLS  = 144;            // LPAD + TW + 8
constexpr int ROWSIN = TH + 2 * RAD;  // 74
constexpr int NGROUP = 7;             // 7*11 = 77 rows swept
constexpr int NTHREADS = 64;
constexpr int F4_PER_ROW   = COLS / 4;          // 36
constexpr int F4_PER_GROUP = F4_PER_ROW * WS;   // 396
constexpr int NBLOCKS = (IMG_W / TW) * (IMG_H / TH) * N_IMG;   // 1536

constexpr float C1f = 0.01f * 0.01f;
constexpr float C2f = 0.03f * 0.03f;

__device__ constexpr float GW[WS] = {
    0.00102838f, 0.00759876f, 0.03600078f, 0.10936070f, 0.21300554f,
    0.26601173f,
    0.21300554f, 0.10936070f, 0.03600078f, 0.00759876f, 0.00102838f
};

__device__ double   g_accum;
__device__ unsigned g_done;

__device__ __forceinline__ void cpa16(void* smem_dst, const void* gmem_src, bool pred)
{
    unsigned s = (unsigned)__cvta_generic_to_shared(smem_dst);
    int n = pred ? 16 : 0;   // src-size 0 -> 16B zero-fill
    asm volatile("cp.async.cg.shared.global [%0], [%1], 16, %2;\n"
                 :: "r"(s), "l"(gmem_src), "r"(n));
}

__device__ __forceinline__ void issue_group(
    int g, int buf, int t, int x0, int y0,
    const float* __restrict__ p1, const float* __restrict__ p2,
    float (*s1)[WS][COLS], float (*s2)[WS][COLS])
{
    #pragma unroll
    for (int q = t; q < F4_PER_GROUP; q += NTHREADS) {
        const int r   = q / F4_PER_ROW;
        const int c4  = q - r * F4_PER_ROW;
        const int y   = y0 - RAD + g * WS + r;
        const int col = x0 - LPAD + c4 * 4;
        const bool ok = ((unsigned)y < (unsigned)IMG_H) &&
                        ((unsigned)col <= (unsigned)(IMG_W - 4));
        const long off = (long)y * IMG_W + col;
        cpa16(&s1[buf][r][c4 * 4], p1 + off, ok);
        cpa16(&s2[buf][r][c4 * 4], p2 + off, ok);
    }
}

__global__ void __launch_bounds__(NTHREADS, 7)
ssim_main_kernel(const float* __restrict__ img1, const float* __restrict__ img2,
                 float* __restrict__ out)
{
    __shared__ __align__(16) float s1[2][WS][COLS];   // s = a+b
    __shared__ __align__(16) float s2[2][WS][COLS];   // d = a-b
    __shared__ float warp_sums[NTHREADS / 32];

    const int t  = threadIdx.x;
    const int x0 = blockIdx.x * TW;
    const int y0 = blockIdx.y * TH;
    const long imgOff = (long)blockIdx.z * (long)(IMG_H * IMG_W);
    const float* __restrict__ p1 = img1 + imgOff;
    const float* __restrict__ p2 = img2 + imgOff;

    issue_group(0, 0, t, x0, y0, p1, p2, s1, s2);
    asm volatile("cp.async.commit_group;\n");
    issue_group(1, 1, t, x0, y0, p1, p2, s1, s2);
    asm volatile("cp.async.commit_group;\n");

    // ring[ph][m]: m = {s0,s1,d0,d1,ss0,ss1,dd0,dd1}  (0/1 = column parity)
    float ring[WS][8];
    float acc = 0.0f;

    for (int g = 0; g < NGROUP; ++g) {
        const int buf = g & 1;
        asm volatile("cp.async.wait_group 1;\n" ::: "memory");
        __syncthreads();                 // raw a,b rows for group g landed

        // ---- in-place transform a,b -> s=a+b, d=a-b (float4) ----
        {
            float4* a4 = reinterpret_cast<float4*>(&s1[buf][0][0]);
            float4* b4 = reinterpret_cast<float4*>(&s2[buf][0][0]);
            #pragma unroll
            for (int i = t; i < F4_PER_GROUP; i += NTHREADS) {
                const float4 a = a4[i];
                const float4 b = b4[i];
                float4 s, d;
                s.x = a.x + b.x; s.y = a.y + b.y; s.z = a.z + b.z; s.w = a.w + b.w;
                d.x = a.x - b.x; d.y = a.y - b.y; d.z = a.z - b.z; d.w = a.w - b.w;
                a4[i] = s; b4[i] = d;
            }
        }
        __syncthreads();

        #pragma unroll
        for (int ph = 0; ph < WS; ++ph) {
            const int ir = g * WS + ph;
            if (ir < ROWSIN) {
                // window: local floats [2t+2 .. 2t+15]; col0 uses j=1..11
                // (tap j-1), col1 uses j=2..12 (tap j-2).
                const float2* rs = reinterpret_cast<const float2*>(&s1[buf][ph][2 * t + 2]);
                const float2* rd = reinterpret_cast<const float2*>(&s2[buf][ph][2 * t + 2]);
                float ws_[14], wd_[14];
                #pragma unroll
                for (int j = 0; j < 7; ++j) {
                    const float2 a = rs[j];
                    const float2 b = rd[j];
                    ws_[2 * j] = a.x; ws_[2 * j + 1] = a.y;
                    wd_[2 * j] = b.x; wd_[2 * j + 1] = b.y;
                }

                float hs0 = 0.f, hs1 = 0.f, hd0 = 0.f, hd1 = 0.f;
                float hss0 = 0.f, hss1 = 0.f, hdd0 = 0.f, hdd1 = 0.f;
                #pragma unroll
                for (int j = 1; j <= 12; ++j) {
                    const float vs = ws_[j];
                    const float vd = wd_[j];
                    const float qs = vs * vs;
                    const float qd = vd * vd;
                    if (j <= 11) {               // col0, tap j-1
                        const float w = GW[j - 1];
                        hs0  = fmaf(w, vs, hs0);
                        hd0  = fmaf(w, vd, hd0);
                        hss0 = fmaf(w, qs, hss0);
                        hdd0 = fmaf(w, qd, hdd0);
                    }
                    if (j >= 2) {                // col1, tap j-2
                        const float w = GW[j - 2];
                        hs1  = fmaf(w, vs, hs1);
                        hd1  = fmaf(w, vd, hd1);
                        hss1 = fmaf(w, qs, hss1);
                        hdd1 = fmaf(w, qd, hdd1);
                    }
                }
                ring[ph][0] = hs0;  ring[ph][1] = hs1;
                ring[ph][2] = hd0;  ring[ph][3] = hd1;
                ring[ph][4] = hss0; ring[ph][5] = hss1;
                ring[ph][6] = hdd0; ring[ph][7] = hdd1;

                // ---- vertical conv from ring + SSIM for both columns ----
                if (ir >= WS - 1) {
                    float m0a = 0.f, m0b = 0.f, m1a = 0.f, m1b = 0.f;
                    float m2a = 0.f, m2b = 0.f, m3a = 0.f, m3b = 0.f;
                    #pragma unroll
                    for (int k = 0; k < WS; ++k) {
                        const int s = (ph + 1 + k) % WS;
                        const float w = GW[k];
                        m0a = fmaf(w, ring[s][0], m0a);
                        m0b = fmaf(w, ring[s][1], m0b);
                        m1a = fmaf(w, ring[s][2], m1a);
                        m1b = fmaf(w, ring[s][3], m1b);
                        m2a = fmaf(w, ring[s][4], m2a);
                        m2b = fmaf(w, ring[s][5], m2b);
                        m3a = fmaf(w, ring[s][6], m3a);
                        m3b = fmaf(w, ring[s][7], m3b);
                    }
                    // col 0
                    {
                        const float P  = m0a * m0a;
                        const float Q  = m1a * m1a;
                        const float SP = P + Q, SM = P - Q;
                        const float ES = m2a + m3a, ED = m2a - m3a;
                        const float n1 = fmaf(SM, 0.5f, C1f);
                        const float n2 = fmaf(ED - SM, 0.5f, C2f);
                        const float d1 = fmaf(SP, 0.5f, C1f);
                        const float d2 = fmaf(ES - SP, 0.5f, C2f);
                        acc += __fdividef(n1 * n2, d1 * d2);
                    }
                    // col 1
                    {
                        const float P  = m0b * m0b;
                        const float Q  = m1b * m1b;
                        const float SP = P + Q, SM = P - Q;
                        const float ES = m2b + m3b, ED = m2b - m3b;
                        const float n1 = fmaf(SM, 0.5f, C1f);
                        const float n2 = fmaf(ED - SM, 0.5f, C2f);
                        const float d1 = fmaf(SP, 0.5f, C1f);
                        const float d2 = fmaf(ES - SP, 0.5f, C2f);
                        acc += __fdividef(n1 * n2, d1 * d2);
                    }
                }
            }
        }

        __syncthreads();
        if (g + 2 < NGROUP)
            issue_group(g + 2, buf, t, x0, y0, p1, p2, s1, s2);
        asm volatile("cp.async.commit_group;\n");
    }

    // ---- block reduction ----
    #pragma unroll
    for (int o = 16; o > 0; o >>= 1)
        acc += __shfl_down_sync(0xffffffffu, acc, o);
    if ((t & 31) == 0) warp_sums[t >> 5] = acc;
    __syncthreads();

    if (t == 0) {
        float bs = 0.0f;
        #pragma unroll
        for (int w = 0; w < NTHREADS / 32; ++w) bs += warp_sums[w];
        atomicAdd(&g_accum, (double)bs);
        __threadfence();
        const unsigned ticket = atomicAdd(&g_done, 1u);
        if (ticket == NBLOCKS - 1) {
            __threadfence();
            out[0] = (float)(g_accum *
                     (1.0 / ((double)N_IMG * (double)IMG_H * (double)IMG_W)));
            g_accum = 0.0;
            g_done  = 0u;
        }
    }
}

extern "C" void kernel_launch(void* const* d_in, const int* in_sizes, int n_in,
                              void* d_out, int out_size)
{
    const float* img1 = (const float*)d_in[0];
    const float* img2 = (const float*)d_in[1];
    float* out = (float*)d_out;

    dim3 grid(IMG_W / TW, IMG_H / TH, N_IMG);   // 4 x 8 x 48 = 1536 blocks
    ssim_main_kernel<<<grid, NTHREADS>>>(img1, img2, out);
}

// round 8
// speedup vs baseline: 1.1823x; 1.1823x over previous
#include <cuda_runtime.h>

// SSIM, fused separable 11x11 Gaussian (sigma=1.5), B=16,C=3,H=W=512, fp32.
// Round-7: packed f32x2 on an interleaved (s,d) smem layout. s=a+b, d=a-b
// (4 convs). Per tap: one LDS.64 -> (s,d) pair, mul2 -> (s^2,d^2), 2 FFMA2.
// Ring holds packed pairs (44 regs, same as scalar R5). 128 threads per
// 128x64 tile, cp.async double-buffered 11-row groups, register-staged
// in-place interleave transform, fused finalize via atomic ticket.

using u64 = unsigned long long;

constexpr int IMG_H = 512;
constexpr int IMG_W = 512;
constexpr int N_IMG = 48;
constexpr int RAD   = 5;
constexpr int WS    = 11;
constexpr int TW    = 128;
constexpr int TH    = 64;
constexpr int LPAD  = 8;
constexpr int COLS  = 144;            // raw row width per image (a or b)
constexpr int IW    = 2 * COLS;       // 288: interleaved (s,d) row width
constexpr int ROWSIN = TH + 2 * RAD;  // 74
constexpr int NGROUP = 7;             // 7*11 = 77 rows swept
constexpr int NTHREADS = 128;
constexpr int F4_PER_ROW   = COLS / 4;          // 36
constexpr int F4_PER_GROUP = F4_PER_ROW * WS;   // 396 (per image)
constexpr int U_PER_GROUP  = (IW / 4) * WS;     // 72 * 11 = 792 float4 units
constexpr int U_ITERS      = (U_PER_GROUP + NTHREADS - 1) / NTHREADS;  // 7
constexpr int NBLOCKS = (IMG_W / TW) * (IMG_H / TH) * N_IMG;           // 1536

constexpr float C1f = 0.01f * 0.01f;
constexpr float C2f = 0.03f * 0.03f;

__device__ constexpr float GW[WS] = {
    0.00102838f, 0.00759876f, 0.03600078f, 0.10936070f, 0.21300554f,
    0.26601173f,
    0.21300554f, 0.10936070f, 0.03600078f, 0.00759876f, 0.00102838f
};

__device__ double   g_accum;
__device__ unsigned g_done;

// ---- packed f32x2 helpers ----
__device__ __forceinline__ u64 pk2(float lo, float hi) {
    u64 r; asm("mov.b64 %0, {%1, %2};" : "=l"(r) : "f"(lo), "f"(hi)); return r;
}
__device__ __forceinline__ void upk2(u64 v, float& lo, float& hi) {
    asm("mov.b64 {%0, %1}, %2;" : "=f"(lo), "=f"(hi) : "l"(v));
}
__device__ __forceinline__ u64 fma2(u64 a, u64 b, u64 c) {
    u64 d; asm("fma.rn.f32x2 %0, %1, %2, %3;" : "=l"(d) : "l"(a), "l"(b), "l"(c)); return d;
}
__device__ __forceinline__ u64 mul2(u64 a, u64 b) {
    u64 d; asm("mul.rn.f32x2 %0, %1, %2;" : "=l"(d) : "l"(a), "l"(b)); return d;
}

__device__ __forceinline__ void cpa16(void* smem_dst, const void* gmem_src, bool pred)
{
    unsigned s = (unsigned)__cvta_generic_to_shared(smem_dst);
    int n = pred ? 16 : 0;   // src-size 0 -> 16B zero-fill
    asm volatile("cp.async.cg.shared.global [%0], [%1], 16, %2;\n"
                 :: "r"(s), "l"(gmem_src), "r"(n));
}

__device__ __forceinline__ void issue_group(
    int g, int buf, int t, int x0, int y0,
    const float* __restrict__ p1, const float* __restrict__ p2,
    float (*I)[WS][IW])
{
    #pragma unroll
    for (int q = t; q < F4_PER_GROUP; q += NTHREADS) {
        const int r   = q / F4_PER_ROW;
        const int c4  = q - r * F4_PER_ROW;
        const int y   = y0 - RAD + g * WS + r;
        const int col = x0 - LPAD + c4 * 4;
        const bool ok = ((unsigned)y < (unsigned)IMG_H) &&
                        ((unsigned)col <= (unsigned)(IMG_W - 4));
        const long off = (long)y * IMG_W + col;
        cpa16(&I[buf][r][c4 * 4],        p1 + off, ok);   // a -> first half
        cpa16(&I[buf][r][COLS + c4 * 4], p2 + off, ok);   // b -> second half
    }
}

__global__ void __launch_bounds__(NTHREADS, 4)
ssim_main_kernel(const float* __restrict__ img1, const float* __restrict__ img2,
                 float* __restrict__ out)
{
    // Raw rows land as [a(144) | b(144)]; transform rewrites each row
    // in place as interleaved [s0,d0,s1,d1,...] (288 floats).
    __shared__ __align__(16) float I[2][WS][IW];
    __shared__ float warp_sums[NTHREADS / 32];

    const int t  = threadIdx.x;
    const int x0 = blockIdx.x * TW;
    const int y0 = blockIdx.y * TH;
    const long imgOff = (long)blockIdx.z * (long)(IMG_H * IMG_W);
    const float* __restrict__ p1 = img1 + imgOff;
    const float* __restrict__ p2 = img2 + imgOff;

    issue_group(0, 0, t, x0, y0, p1, p2, I);
    asm volatile("cp.async.commit_group;\n");
    issue_group(1, 1, t, x0, y0, p1, p2, I);
    asm volatile("cp.async.commit_group;\n");

    u64 ring[WS][2];     // [0] = (G*s, G*d) pair, [1] = (G*s^2, G*d^2) pair
    float acc = 0.0f;

    for (int g = 0; g < NGROUP; ++g) {
        const int buf = g & 1;
        asm volatile("cp.async.wait_group 1;\n" ::: "memory");
        __syncthreads();                 // raw a|b rows for group g landed

        // ---- register-staged in-place interleave: a,b -> (s,d) pairs ----
        float4 stg[U_ITERS];
        #pragma unroll
        for (int it = 0; it < U_ITERS; ++it) {
            const int u = t + it * NTHREADS;
            if (u < U_PER_GROUP) {
                const int r = u / (IW / 4);
                const int p = u - r * (IW / 4);
                const float2 a = *reinterpret_cast<const float2*>(&I[buf][r][2 * p]);
                const float2 b = *reinterpret_cast<const float2*>(&I[buf][r][COLS + 2 * p]);
                stg[it] = make_float4(a.x + b.x, a.x - b.x,
                                      a.y + b.y, a.y - b.y);
            }
        }
        __syncthreads();                 // all raw reads complete
        #pragma unroll
        for (int it = 0; it < U_ITERS; ++it) {
            const int u = t + it * NTHREADS;
            if (u < U_PER_GROUP) {
                const int r = u / (IW / 4);
                const int p = u - r * (IW / 4);
                *reinterpret_cast<float4*>(&I[buf][r][4 * p]) = stg[it];
            }
        }
        __syncthreads();                 // interleaved rows visible

        #pragma unroll
        for (int ph = 0; ph < WS; ++ph) {
            const int ir = g * WS + ph;
            if (ir < ROWSIN) {
                // (s,d) pairs for window cols t+3 .. t+13 (8B-aligned)
                const u64* rp = reinterpret_cast<const u64*>(&I[buf][ph][2 * (t + 3)]);

                // -- horizontal 11-tap conv, packed --
                u64 h_sd = 0ull, h_qq = 0ull;
                #pragma unroll
                for (int k = 0; k < WS; ++k) {
                    const u64 w2 = pk2(GW[k], GW[k]);   // 6 unique consts
                    const u64 v  = rp[k];
                    h_sd = fma2(w2, v, h_sd);
                    h_qq = fma2(w2, mul2(v, v), h_qq);
                }
                ring[ph][0] = h_sd;
                ring[ph][1] = h_qq;

                // -- vertical 11-tap conv from packed ring + SSIM --
                if (ir >= WS - 1) {
                    u64 m_sd = 0ull, m_qq = 0ull;
                    #pragma unroll
                    for (int k = 0; k < WS; ++k) {
                        const int s = (ph + 1 + k) % WS;
                        const u64 w2 = pk2(GW[k], GW[k]);
                        m_sd = fma2(w2, ring[s][0], m_sd);
                        m_qq = fma2(w2, ring[s][1], m_qq);
                    }
                    float Gs, Gd, Gss, Gdd;
                    upk2(m_sd, Gs, Gd);
                    upk2(m_qq, Gss, Gdd);
                    const float P  = Gs * Gs;            // (G*s)^2
                    const float Q  = Gd * Gd;            // (G*d)^2
                    const float SP = P + Q;              // 2(mu1^2+mu2^2)
                    const float SM = P - Q;              // 4 mu1 mu2
                    const float ES = Gss + Gdd;          // 2 E[x1^2+x2^2]
                    const float ED = Gss - Gdd;          // 4 E[x1 x2]
                    const float n1 = fmaf(SM, 0.5f, C1f);        // 2mu1mu2+C1
                    const float n2 = fmaf(ED - SM, 0.5f, C2f);   // 2sig12+C2
                    const float d1 = fmaf(SP, 0.5f, C1f);        // mu^2 sum+C1
                    const float d2 = fmaf(ES - SP, 0.5f, C2f);   // sig sum+C2
                    acc += __fdividef(n1 * n2, d1 * d2);
                }
            }
        }

        __syncthreads();                 // buffer consumed
        if (g + 2 < NGROUP)
            issue_group(g + 2, buf, t, x0, y0, p1, p2, I);
        asm volatile("cp.async.commit_group;\n");
    }

    // ---- block reduction ----
    #pragma unroll
    for (int o = 16; o > 0; o >>= 1)
        acc += __shfl_down_sync(0xffffffffu, acc, o);
    if ((t & 31) == 0) warp_sums[t >> 5] = acc;
    __syncthreads();

    if (t == 0) {
        float bs = 0.0f;
        #pragma unroll
        for (int w = 0; w < NTHREADS / 32; ++w) bs += warp_sums[w];
        atomicAdd(&g_accum, (double)bs);
        __threadfence();
        const unsigned ticket = atomicAdd(&g_done, 1u);
        if (ticket == NBLOCKS - 1) {
            __threadfence();
            out[0] = (float)(g_accum *
                     (1.0 / ((double)N_IMG * (double)IMG_H * (double)IMG_W)));
            g_accum = 0.0;
            g_done  = 0u;
        }
    }
}

extern "C" void kernel_launch(void* const* d_in, const int* in_sizes, int n_in,
                              void* d_out, int out_size)
{
    const float* img1 = (const float*)d_in[0];
    const float* img2 = (const float*)d_in[1];
    float* out = (float*)d_out;

    dim3 grid(IMG_W / TW, IMG_H / TH, N_IMG);   // 4 x 8 x 48 = 1536 blocks
    ssim_main_kernel<<<grid, NTHREADS>>>(img1, img2, out);
}

// round 9
// speedup vs baseline: 1.6831x; 1.4236x over previous
#include <cuda_runtime.h>

// SSIM, fused separable 11x11 Gaussian (sigma=1.5), B=16,C=3,H=W=512, fp32.
// Round-9: R5 scalar chassis + squares computed ONCE per pixel. Transform
// writes (s, d, s^2, d^2) as one float4 per column; horizontal conv is
// 11 LDS.128 + 44 FFMA-imm per phase (was 22 LDS + 22 FMUL + 44 FFMA).
// 128 threads per 128x64 tile, cp.async double-buffered raw rows, single
// transformed buffer, scalar ring, fused finalize via atomic ticket.

constexpr int IMG_H = 512;
constexpr int IMG_W = 512;
constexpr int N_IMG = 48;
constexpr int RAD   = 5;
constexpr int WS    = 11;
constexpr int TW    = 128;
constexpr int TH    = 64;
constexpr int LPAD  = 8;
constexpr int COLS  = 144;            // working columns per row
constexpr int RAWW  = 2 * COLS;       // raw row: [a(144) | b(144)]
constexpr int ROWSIN = TH + 2 * RAD;  // 74
constexpr int NGROUP = 7;             // 7*11 = 77 rows swept
constexpr int NTHREADS = 128;
constexpr int F4_PER_ROW   = COLS / 4;          // 36
constexpr int F4_PER_GROUP = F4_PER_ROW * WS;   // 396 (per image)
constexpr int PIX_PER_GROUP = COLS * WS;        // 1584
constexpr int T_ITERS = (PIX_PER_GROUP + NTHREADS - 1) / NTHREADS;  // 13
constexpr int NBLOCKS = (IMG_W / TW) * (IMG_H / TH) * N_IMG;        // 1536

constexpr float C1f = 0.01f * 0.01f;
constexpr float C2f = 0.03f * 0.03f;

__device__ constexpr float GW[WS] = {
    0.00102838f, 0.00759876f, 0.03600078f, 0.10936070f, 0.21300554f,
    0.26601173f,
    0.21300554f, 0.10936070f, 0.03600078f, 0.00759876f, 0.00102838f
};

__device__ double   g_accum;
__device__ unsigned g_done;

__device__ __forceinline__ void cpa16(void* smem_dst, const void* gmem_src, bool pred)
{
    unsigned s = (unsigned)__cvta_generic_to_shared(smem_dst);
    int n = pred ? 16 : 0;   // src-size 0 -> 16B zero-fill
    asm volatile("cp.async.cg.shared.global [%0], [%1], 16, %2;\n"
                 :: "r"(s), "l"(gmem_src), "r"(n));
}

__device__ __forceinline__ void issue_group(
    int g, int buf, int t, int x0, int y0,
    const float* __restrict__ p1, const float* __restrict__ p2,
    float (*raw)[WS][RAWW])
{
    #pragma unroll
    for (int q = t; q < F4_PER_GROUP; q += NTHREADS) {
        const int r   = q / F4_PER_ROW;
        const int c4  = q - r * F4_PER_ROW;
        const int y   = y0 - RAD + g * WS + r;
        const int col = x0 - LPAD + c4 * 4;
        const bool ok = ((unsigned)y < (unsigned)IMG_H) &&
                        ((unsigned)col <= (unsigned)(IMG_W - 4));
        const long off = (long)y * IMG_W + col;
        cpa16(&raw[buf][r][c4 * 4],        p1 + off, ok);
        cpa16(&raw[buf][r][COLS + c4 * 4], p2 + off, ok);
    }
}

__global__ void __launch_bounds__(NTHREADS, 4)
ssim_main_kernel(const float* __restrict__ img1, const float* __restrict__ img2,
                 float* __restrict__ out)
{
    __shared__ __align__(16) float  raw[2][WS][RAWW];   // double-buffered a|b
    __shared__ __align__(16) float4 T[WS][COLS];        // (s, d, s^2, d^2)
    __shared__ float warp_sums[NTHREADS / 32];

    const int t  = threadIdx.x;
    const int x0 = blockIdx.x * TW;
    const int y0 = blockIdx.y * TH;
    const long imgOff = (long)blockIdx.z * (long)(IMG_H * IMG_W);
    const float* __restrict__ p1 = img1 + imgOff;
    const float* __restrict__ p2 = img2 + imgOff;

    issue_group(0, 0, t, x0, y0, p1, p2, raw);
    asm volatile("cp.async.commit_group;\n");
    issue_group(1, 1, t, x0, y0, p1, p2, raw);
    asm volatile("cp.async.commit_group;\n");

    float ring[WS][4];     // horizontal conv results: G*s, G*d, G*s^2, G*d^2
    float acc = 0.0f;

    for (int g = 0; g < NGROUP; ++g) {
        const int buf = g & 1;
        asm volatile("cp.async.wait_group 1;\n" ::: "memory");
        __syncthreads();                 // raw rows landed; prev compute done

        // ---- transform: (a,b) -> float4(s, d, s*s, d*d), once per pixel ----
        #pragma unroll
        for (int it = 0; it < T_ITERS; ++it) {
            const int u = t + it * NTHREADS;
            if (u < PIX_PER_GROUP) {
                const int r = u / COLS;
                const int c = u - r * COLS;
                const float a = raw[buf][r][c];
                const float b = raw[buf][r][COLS + c];
                const float s = a + b;
                const float d = a - b;
                T[r][c] = make_float4(s, d, s * s, d * d);
            }
        }
        __syncthreads();                 // transformed rows visible

        #pragma unroll
        for (int ph = 0; ph < WS; ++ph) {
            const int ir = g * WS + ph;
            if (ir < ROWSIN) {
                const float4* __restrict__ rw = &T[ph][t + 3];

                // -- horizontal 11-tap conv of 4 maps: 11 LDS.128 + 44 FFMA --
                float h0 = 0.f, h1 = 0.f, h2 = 0.f, h3 = 0.f;
                #pragma unroll
                for (int k = 0; k < WS; ++k) {
                    const float4 v = rw[k];
                    const float  w = GW[k];
                    h0 = fmaf(w, v.x, h0);
                    h1 = fmaf(w, v.y, h1);
                    h2 = fmaf(w, v.z, h2);
                    h3 = fmaf(w, v.w, h3);
                }
                ring[ph][0] = h0; ring[ph][1] = h1;
                ring[ph][2] = h2; ring[ph][3] = h3;

                // -- vertical 11-tap conv from register ring + SSIM --
                if (ir >= WS - 1) {
                    float m0 = 0.f, m1 = 0.f, m2 = 0.f, m3 = 0.f;
                    #pragma unroll
                    for (int k = 0; k < WS; ++k) {
                        const int s = (ph + 1 + k) % WS;
                        const float w = GW[k];
                        m0 = fmaf(w, ring[s][0], m0);
                        m1 = fmaf(w, ring[s][1], m1);
                        m2 = fmaf(w, ring[s][2], m2);
                        m3 = fmaf(w, ring[s][3], m3);
                    }
                    const float P  = m0 * m0;            // (G*s)^2
                    const float Q  = m1 * m1;            // (G*d)^2
                    const float SP = P + Q;              // 2(mu1^2+mu2^2)
                    const float SM = P - Q;              // 4 mu1 mu2
                    const float ES = m2 + m3;            // 2 E[x1^2+x2^2]
                    const float ED = m2 - m3;            // 4 E[x1 x2]
                    const float n1 = fmaf(SM, 0.5f, C1f);        // 2mu1mu2+C1
                    const float n2 = fmaf(ED - SM, 0.5f, C2f);   // 2sig12+C2
                    const float d1 = fmaf(SP, 0.5f, C1f);        // mu^2 sum+C1
                    const float d2 = fmaf(ES - SP, 0.5f, C2f);   // sig sum+C2
                    acc += __fdividef(n1 * n2, d1 * d2);
                }
            }
        }

        __syncthreads();                 // compute done -> T may be rewritten
        if (g + 2 < NGROUP)
            issue_group(g + 2, buf, t, x0, y0, p1, p2, raw);
        asm volatile("cp.async.commit_group;\n");
    }

    // ---- block reduction ----
    #pragma unroll
    for (int o = 16; o > 0; o >>= 1)
        acc += __shfl_down_sync(0xffffffffu, acc, o);
    if ((t & 31) == 0) warp_sums[t >> 5] = acc;
    __syncthreads();

    if (t == 0) {
        float bs = 0.0f;
        #pragma unroll
        for (int w = 0; w < NTHREADS / 32; ++w) bs += warp_sums[w];
        atomicAdd(&g_accum, (double)bs);
        __threadfence();
        const unsigned ticket = atomicAdd(&g_done, 1u);
        if (ticket == NBLOCKS - 1) {
            __threadfence();
            out[0] = (float)(g_accum *
                     (1.0 / ((double)N_IMG * (double)IMG_H * (double)IMG_W)));
            g_accum = 0.0;
            g_done  = 0u;
        }
    }
}

extern "C" void kernel_launch(void* const* d_in, const int* in_sizes, int n_in,
                              void* d_out, int out_size)
{
    const float* img1 = (const float*)d_in[0];
    const float* img2 = (const float*)d_in[1];
    float* out = (float*)d_out;

    dim3 grid(IMG_W / TW, IMG_H / TH, N_IMG);   // 4 x 8 x 48 = 1536 blocks
    ssim_main_kernel<<<grid, NTHREADS>>>(img1, img2, out);
}